// round 17
// baseline (speedup 1.0000x reference)
#include <cuda_runtime.h>
#include <math.h>
#include <stdint.h>

#define D_DIM 256
#define K_CB  1024
#define N_VEC 65536
#define DELTA 6e-4f

__device__ float        g_enorm[K_CB];
__device__ unsigned int g_counts[K_CB];
__device__ double       g_sumsq;
__device__ int          g_idx[N_VEC];
__device__ int          g_flags[N_VEC];     // cheap list (top-4 certified)
__device__ int          g_flags2[N_VEC];    // full-recheck list (rare)
__device__ int          g_nflag;
__device__ int          g_nflag2;
__device__ int4         g_cand[N_VEC];      // top-4 candidate indices per flagged row
__device__ uint2        g_eb[K_CB * 64];    // e as bf16 (512 KB)

// ---------------------------------------------------------------------------
__device__ __forceinline__ uint32_t smem_u32(const void* p) {
    uint32_t a;
    asm("{ .reg .u64 t; cvta.to.shared.u64 t, %1; cvt.u32.u64 %0, t; }"
        : "=r"(a) : "l"(p));
    return a;
}
__device__ __forceinline__ void cp16(uint32_t dst, const void* src) {
    asm volatile("cp.async.cg.shared.global [%0], [%1], 16;" :: "r"(dst), "l"(src));
}
#define CP_COMMIT() asm volatile("cp.async.commit_group;")
template <int N> __device__ __forceinline__ void cp_wait() {
    asm volatile("cp.async.wait_group %0;" :: "n"(N));
}
__device__ __forceinline__ void mma_bf16(float* c, uint32_t a0, uint32_t a1,
                                         uint32_t a2, uint32_t a3,
                                         uint32_t b0, uint32_t b1) {
    asm("mma.sync.aligned.m16n8k16.row.col.f32.bf16.bf16.f32 "
        "{%0,%1,%2,%3},{%4,%5,%6,%7},{%8,%9},{%0,%1,%2,%3};"
        : "+f"(c[0]), "+f"(c[1]), "+f"(c[2]), "+f"(c[3])
        : "r"(a0), "r"(a1), "r"(a2), "r"(a3), "r"(b0), "r"(b1));
}
__device__ __forceinline__ uint32_t bf16x2(float lo, float hi) {
    uint32_t r;
    asm("cvt.rn.bf16x2.f32 %0, %1, %2;" : "=r"(r) : "f"(hi), "f"(lo));
    return r;
}
// insert (k,i) into ascending top-4 list; strict < (equal-key evictions are
// safe: any ambiguity forces m4-m1 <= DELTA -> full recheck)
__device__ __forceinline__ void ins4(float* mk, int* mi, float k, int i) {
    if (k < mk[3]) {
        mk[3] = k; mi[3] = i;
        if (mk[3] < mk[2]) { float tk = mk[2]; mk[2] = mk[3]; mk[3] = tk;
                             int ti = mi[2]; mi[2] = mi[3]; mi[3] = ti; }
        if (mk[2] < mk[1]) { float tk = mk[1]; mk[1] = mk[2]; mk[2] = tk;
                             int ti = mi[1]; mi[1] = mi[2]; mi[2] = ti; }
        if (mk[1] < mk[0]) { float tk = mk[0]; mk[0] = mk[1]; mk[1] = tk;
                             int ti = mi[0]; mi[0] = mi[1]; mi[1] = ti; }
    }
}

__global__ void vq_zero_kernel() {
    int t = threadIdx.x;
    if (t < K_CB) g_counts[t] = 0u;
    if (t == 0) { g_sumsq = 0.0; g_nflag = 0; g_nflag2 = 0; }
}

// convert e -> bf16 + row norms (f32). 256 blocks x 256 thr
__global__ void vq_cvt_e_enorm(const float* __restrict__ e) {
    __shared__ float part[8];
    int b = blockIdx.x, t = threadIdx.x;
    int i = b * 256 + t;
    float4 v = ((const float4*)e)[i];
    g_eb[i] = make_uint2(bf16x2(v.x, v.y), bf16x2(v.z, v.w));
    float s = v.x * v.x + v.y * v.y + v.z * v.z + v.w * v.w;
    #pragma unroll
    for (int m = 16; m; m >>= 1) s += __shfl_xor_sync(~0u, s, m);
    int w = t >> 5;
    if ((t & 31) == 0) part[w] = s;
    __syncthreads();
    if (t < 4) g_enorm[b * 4 + t] = part[2 * t] + part[2 * t + 1];
}

// ---------------------------------------------------------------------------
// Screen: bf16 GEMM (m16n8k16), in-kernel x f32->bf16, per-row TOP-4 fold,
//   fused gather/MSE/hist. CTA = 128 rows x 256-col passes, 512 thr, 16 warps.
// ---------------------------------------------------------------------------
#define XPW 132
#define EPW 36
#define ES_BUFW 9216
#define OFF_XS   0
#define OFF_ES   16896
#define OFF_REDK 35328          /* 128*4 float4 = 2048 */
#define OFF_REDI 37376          /* 128*4 int4   = 2048 */
#define OFF_BMK  39424          /* 128*4 */
#define OFF_BMI  39936          /* 128*4 */
#define OFF_ENS  40448          /* 256 */
#define SM_FLOATS 40704         /* 162816 bytes */

__global__ void __launch_bounds__(512, 1) vq_screen_kernel(
    const float* __restrict__ x, const float* __restrict__ e,
    float* __restrict__ out)
{
    extern __shared__ float sm[];
    uint32_t* xw   = (uint32_t*)sm;
    float4*   redk = (float4*)(sm + OFF_REDK);
    int4*     redi = (int4*)(sm + OFF_REDI);
    float*    bmk  = sm + OFF_BMK;          // [128][4]
    int*      bmi  = (int*)(sm + OFF_BMI);  // [128][4]
    float*    ens  = sm + OFF_ENS;

    const int t = threadIdx.x, wid = t >> 5, lane = t & 31;
    const int wm = wid >> 2, wn = wid & 3;
    const int g = lane >> 2, tig = lane & 3;
    const int rb0 = blockIdx.x * 128;
    const uint32_t sb = smem_u32(sm);

    {   // x tile: LDG f32 -> cvt bf16 -> STS
        const float4* xsrc = (const float4*)x + (size_t)rb0 * 64;
        #pragma unroll
        for (int i = 0; i < 16; i++) {
            int idx = t + i * 512;
            int row = idx >> 6, f4 = idx & 63;
            float4 v = xsrc[(size_t)row * 64 + f4];
            uint32_t* dst = xw + row * XPW + f4 * 2;
            dst[0] = bf16x2(v.x, v.y);
            dst[1] = bf16x2(v.z, v.w);
        }
    }

    if (t < 128) {
        #pragma unroll
        for (int q = 0; q < 4; q++) { bmk[t * 4 + q] = 3.4e38f; bmi[t * 4 + q] = 0x7fffffff; }
    }
    if (t < 256) ens[t] = g_enorm[t];

    auto issue_e = [&](int cc) {
        int ct4 = cc >> 2, ch = cc & 3, buf = cc & 1;
        #pragma unroll
        for (int i = 0; i < 4; i++) {
            int idx = t + i * 512;
            int n = idx >> 3, c16 = idx & 7;
            cp16(sb + (uint32_t)((OFF_ES + buf * ES_BUFW + n * EPW + c16 * 4) * 4),
                 (const uint2*)g_eb + (size_t)(ct4 * 256 + n) * 64 + ch * 16 + c16 * 2);
        }
        CP_COMMIT();
    };
    issue_e(0); issue_e(1);

    float acc[2][8][4];

    for (int cc = 0; cc < 16; cc++) {
        const int ct4 = cc >> 2, ch = cc & 3, buf = cc & 1;
        if (ch == 0) {
            #pragma unroll
            for (int mt = 0; mt < 2; mt++)
                #pragma unroll
                for (int nt = 0; nt < 8; nt++)
                    #pragma unroll
                    for (int j = 0; j < 4; j++) acc[mt][nt][j] = 0.f;
        }
        if (cc < 15) cp_wait<1>(); else cp_wait<0>();
        __syncthreads();

        {
            const uint32_t* eB = xw + OFF_ES + buf * ES_BUFW
                               + (wn * 64 + g) * EPW + tig;
            const uint32_t* xA = xw + (wm * 32 + g) * XPW + ch * 32 + tig;
            #pragma unroll
            for (int ks = 0; ks < 4; ks++) {
                const int o = ks * 8;
                uint32_t a0[4], a1[4];
                a0[0] = xA[o];
                a0[1] = xA[8 * XPW + o];
                a0[2] = xA[o + 4];
                a0[3] = xA[8 * XPW + o + 4];
                a1[0] = xA[16 * XPW + o];
                a1[1] = xA[24 * XPW + o];
                a1[2] = xA[16 * XPW + o + 4];
                a1[3] = xA[24 * XPW + o + 4];
                #pragma unroll
                for (int nt = 0; nt < 8; nt++) {
                    uint32_t b0 = eB[nt * 8 * EPW + o];
                    uint32_t b1 = eB[nt * 8 * EPW + o + 4];
                    mma_bf16(acc[0][nt], a0[0], a0[1], a0[2], a0[3], b0, b1);
                    mma_bf16(acc[1][nt], a1[0], a1[1], a1[2], a1[3], b0, b1);
                }
            }
        }
        __syncthreads();
        if (cc + 2 < 16) issue_e(cc + 2);

        // ---- per-pass TOP-4 fold after the pass's last chunk (256 cols)
        if (ch == 3) {
            #pragma unroll
            for (int mt = 0; mt < 2; mt++) {
                float mkl[4], mkh[4]; int mil[4], mih[4];
                #pragma unroll
                for (int q = 0; q < 4; q++) {
                    mkl[q] = 3.4e38f; mkh[q] = 3.4e38f;
                    mil[q] = 0x7fffffff; mih[q] = 0x7fffffff;
                }
                #pragma unroll
                for (int nt = 0; nt < 8; nt++) {
                    int col = wn * 64 + nt * 8 + 2 * tig;
                    int gi  = ct4 * 256 + col;
                    ins4(mkl, mil, fmaf(-2.f, acc[mt][nt][0], ens[col]),     gi);
                    ins4(mkl, mil, fmaf(-2.f, acc[mt][nt][1], ens[col + 1]), gi + 1);
                    ins4(mkh, mih, fmaf(-2.f, acc[mt][nt][2], ens[col]),     gi);
                    ins4(mkh, mih, fmaf(-2.f, acc[mt][nt][3], ens[col + 1]), gi + 1);
                }
                #pragma unroll
                for (int d = 1; d <= 2; d <<= 1) {   // symmetric merge in tig group
                    float ok[4]; int oi[4];
                    #pragma unroll
                    for (int q = 0; q < 4; q++) {
                        ok[q] = __shfl_xor_sync(~0u, mkl[q], d);
                        oi[q] = __shfl_xor_sync(~0u, mil[q], d);
                    }
                    #pragma unroll
                    for (int q = 0; q < 4; q++) ins4(mkl, mil, ok[q], oi[q]);
                    #pragma unroll
                    for (int q = 0; q < 4; q++) {
                        ok[q] = __shfl_xor_sync(~0u, mkh[q], d);
                        oi[q] = __shfl_xor_sync(~0u, mih[q], d);
                    }
                    #pragma unroll
                    for (int q = 0; q < 4; q++) ins4(mkh, mih, ok[q], oi[q]);
                }
                if (tig == 0) {
                    int rl = wm * 32 + mt * 16 + g;
                    redk[rl * 4 + wn]       = make_float4(mkl[0], mkl[1], mkl[2], mkl[3]);
                    redi[rl * 4 + wn]       = make_int4(mil[0], mil[1], mil[2], mil[3]);
                    redk[(rl + 8) * 4 + wn] = make_float4(mkh[0], mkh[1], mkh[2], mkh[3]);
                    redi[(rl + 8) * 4 + wn] = make_int4(mih[0], mih[1], mih[2], mih[3]);
                }
            }
            __syncthreads();
            if (t < 128) {      // merge pass top-4 into running top-4
                float bk4[4]; int bi4[4];
                #pragma unroll
                for (int q = 0; q < 4; q++) { bk4[q] = bmk[t * 4 + q]; bi4[q] = bmi[t * 4 + q]; }
                #pragma unroll
                for (int q = 0; q < 4; q++) {
                    float4 kk = redk[t * 4 + q];
                    int4   ii = redi[t * 4 + q];
                    ins4(bk4, bi4, kk.x, ii.x);
                    ins4(bk4, bi4, kk.y, ii.y);
                    ins4(bk4, bi4, kk.z, ii.z);
                    ins4(bk4, bi4, kk.w, ii.w);
                }
                #pragma unroll
                for (int q = 0; q < 4; q++) { bmk[t * 4 + q] = bk4[q]; bmi[t * 4 + q] = bi4[q]; }
            }
            if (t < 256 && ct4 < 3) ens[t] = g_enorm[(ct4 + 1) * 256 + t];
        }
    }
    __syncthreads();

    // ---- winners: indices, histogram, flags (cheap vs full)
    if (t < 128) {
        int k = bmi[t * 4 + 0];
        g_idx[rb0 + t] = k;
        atomicAdd(&g_counts[k], 1u);
        float m1 = bmk[t * 4 + 0];
        if (bmk[t * 4 + 3] - m1 <= DELTA) {          // top-4 can't certify -> full
            int s = atomicAdd(&g_nflag2, 1);
            g_flags2[s] = rb0 + t;
        } else if (bmk[t * 4 + 1] - m1 <= DELTA) {   // winner among top-4
            int s = atomicAdd(&g_nflag, 1);
            g_flags[s] = rb0 + t;
            g_cand[rb0 + t] = make_int4(bmi[t * 4 + 0], bmi[t * 4 + 1],
                                        bmi[t * 4 + 2], bmi[t * 4 + 3]);
        }
    }
    __syncthreads();

    // ---- fused gather + straight-through out + MSE
    float mse = 0.f;
    #pragma unroll
    for (int r8 = 0; r8 < 8; r8++) {
        int row = wid * 8 + r8;
        int k = bmi[row * 4 + 0];
        const float4* er = (const float4*)e + (size_t)k * 64;
        const float4* xr = (const float4*)x + (size_t)(rb0 + row) * 64;
        float4* orow = (float4*)out + (size_t)(rb0 + row) * 64;
        #pragma unroll
        for (int q = 0; q < 2; q++) {
            int i = lane + q * 32;
            float4 qv = er[i];
            float4 xv = xr[i];
            float4 ov;
            float d0 = __fadd_rn(qv.x, -xv.x); ov.x = __fadd_rn(xv.x, d0);
            float d1 = __fadd_rn(qv.y, -xv.y); ov.y = __fadd_rn(xv.y, d1);
            float d2 = __fadd_rn(qv.z, -xv.z); ov.z = __fadd_rn(xv.z, d2);
            float d3 = __fadd_rn(qv.w, -xv.w); ov.w = __fadd_rn(xv.w, d3);
            orow[i] = ov;
            mse = fmaf(d0, d0, mse); mse = fmaf(d1, d1, mse);
            mse = fmaf(d2, d2, mse); mse = fmaf(d3, d3, mse);
        }
    }
    #pragma unroll
    for (int m = 16; m; m >>= 1) mse += __shfl_xor_sync(~0u, mse, m);
    float* redf = sm + OFF_REDK;       // reuse (top-4 merge is done)
    if (lane == 0) redf[wid] = mse;
    __syncthreads();
    if (t < 16) {
        float s = redf[t];
        #pragma unroll
        for (int m = 8; m; m >>= 1) s += __shfl_xor_sync(0x0000ffffu, s, m);
        if (t == 0) atomicAdd(&g_sumsq, (double)s);
    }
}

// ---------------------------------------------------------------------------
// Cheap recheck: 1 thread per flagged row, exact keys for its <=4 candidates.
//   Serial ascending-d fma chain per candidate (bit-exact vs reference),
//   key = fl(fl(A+B) - 2*M), lowest-index ties. Repairs out/counts/sumsq.
// ---------------------------------------------------------------------------
__global__ void vq_cheap_kernel(const float* __restrict__ x,
                                const float* __restrict__ e,
                                float* __restrict__ out)
{
    const int n = g_nflag;
    for (int i = blockIdx.x * blockDim.x + threadIdx.x; i < n;
         i += gridDim.x * blockDim.x) {
        int row = g_flags[i];
        int4 cd = g_cand[row];
        const float* xr = x + (size_t)row * D_DIM;
        const float* p0 = e + (size_t)cd.x * D_DIM;
        const float* p1 = e + (size_t)cd.y * D_DIM;
        const float* p2 = e + (size_t)cd.z * D_DIM;
        const float* p3 = e + (size_t)cd.w * D_DIM;
        float A = 0.f, s0 = 0.f, s1 = 0.f, s2 = 0.f, s3 = 0.f;
        #pragma unroll 8
        for (int d = 0; d < D_DIM; d++) {
            float xv = __ldg(xr + d);
            A  = fmaf(xv, xv, A);
            s0 = fmaf(xv, __ldg(p0 + d), s0);
            s1 = fmaf(xv, __ldg(p1 + d), s1);
            s2 = fmaf(xv, __ldg(p2 + d), s2);
            s3 = fmaf(xv, __ldg(p3 + d), s3);
        }
        float k0 = __fadd_rn(__fadd_rn(A, g_enorm[cd.x]), -__fmul_rn(2.f, s0));
        float k1 = __fadd_rn(__fadd_rn(A, g_enorm[cd.y]), -__fmul_rn(2.f, s1));
        float k2 = __fadd_rn(__fadd_rn(A, g_enorm[cd.z]), -__fmul_rn(2.f, s2));
        float k3 = __fadd_rn(__fadd_rn(A, g_enorm[cd.w]), -__fmul_rn(2.f, s3));
        float bk = k0; int bi = cd.x;
        if (k1 < bk || (k1 == bk && cd.y < bi)) { bk = k1; bi = cd.y; }
        if (k2 < bk || (k2 == bk && cd.z < bi)) { bk = k2; bi = cd.z; }
        if (k3 < bk || (k3 == bk && cd.w < bi)) { bk = k3; bi = cd.w; }
        int ko = g_idx[row];
        if (bi != ko) {
            g_idx[row] = bi;
            atomicAdd(&g_counts[ko], 0xFFFFFFFFu);
            atomicAdd(&g_counts[bi], 1u);
            const float* en_ = e + (size_t)bi * D_DIM;
            const float* eo_ = e + (size_t)ko * D_DIM;
            float* orow = out + (size_t)row * D_DIM;
            float ds = 0.f;
            #pragma unroll 8
            for (int d = 0; d < D_DIM; d++) {
                float xv = __ldg(xr + d);
                float nn = __fadd_rn(__ldg(en_ + d), -xv);
                orow[d] = __fadd_rn(xv, nn);
                float oo = __fadd_rn(__ldg(eo_ + d), -xv);
                ds += nn * nn - oo * oo;
            }
            atomicAdd(&g_sumsq, (double)ds);
        }
    }
}

// ---------------------------------------------------------------------------
// Full fallback: 1 block per uncertifiable row (rare). 4 cw/thread, exact
//   serial chains, block reduce, block repair.
// ---------------------------------------------------------------------------
__global__ void __launch_bounds__(256, 1) vq_full_kernel(
    const float* __restrict__ x, const float* __restrict__ e,
    float* __restrict__ out)
{
    __shared__ float xs_[D_DIM];
    __shared__ float wk[8];
    __shared__ int   wi[8];
    __shared__ int   s_kn, s_ko;
    const int n2 = g_nflag2;
    const int t = threadIdx.x, w = t >> 5, lane = t & 31;

    for (int b = blockIdx.x; b < n2; b += gridDim.x) {
        int row = g_flags2[b];
        xs_[t] = x[(size_t)row * D_DIM + t];
        if (t == 0) s_ko = g_idx[row];
        __syncthreads();

        const float* p0 = e + (size_t)(t + 0)   * D_DIM;
        const float* p1 = e + (size_t)(t + 256) * D_DIM;
        const float* p2 = e + (size_t)(t + 512) * D_DIM;
        const float* p3 = e + (size_t)(t + 768) * D_DIM;
        float A = 0.f, s0 = 0.f, s1 = 0.f, s2 = 0.f, s3 = 0.f;
        #pragma unroll 8
        for (int d = 0; d < D_DIM; d++) {
            float xv = xs_[d];
            A  = fmaf(xv, xv, A);
            s0 = fmaf(xv, __ldg(p0 + d), s0);
            s1 = fmaf(xv, __ldg(p1 + d), s1);
            s2 = fmaf(xv, __ldg(p2 + d), s2);
            s3 = fmaf(xv, __ldg(p3 + d), s3);
        }
        float bk; int bi;
        {
            float k0 = __fadd_rn(__fadd_rn(A, g_enorm[t]),       -__fmul_rn(2.f, s0));
            float k1 = __fadd_rn(__fadd_rn(A, g_enorm[t + 256]), -__fmul_rn(2.f, s1));
            float k2 = __fadd_rn(__fadd_rn(A, g_enorm[t + 512]), -__fmul_rn(2.f, s2));
            float k3 = __fadd_rn(__fadd_rn(A, g_enorm[t + 768]), -__fmul_rn(2.f, s3));
            bk = k0; bi = t;                         // ascending cw in reg order
            if (k1 < bk) { bk = k1; bi = t + 256; }
            if (k2 < bk) { bk = k2; bi = t + 512; }
            if (k3 < bk) { bk = k3; bi = t + 768; }
        }
        #pragma unroll
        for (int d = 16; d; d >>= 1) {
            float ok = __shfl_xor_sync(~0u, bk, d);
            int   oi = __shfl_xor_sync(~0u, bi, d);
            if (ok < bk || (ok == bk && oi < bi)) { bk = ok; bi = oi; }
        }
        if (lane == 0) { wk[w] = bk; wi[w] = bi; }
        __syncthreads();
        if (t == 0) {
            float m = wk[0]; int im = wi[0];
            #pragma unroll
            for (int q = 1; q < 8; q++)
                if (wk[q] < m || (wk[q] == m && wi[q] < im)) { m = wk[q]; im = wi[q]; }
            s_kn = im;
            if (im != s_ko) {
                g_idx[row] = im;
                atomicAdd(&g_counts[s_ko], 0xFFFFFFFFu);
                atomicAdd(&g_counts[im], 1u);
            }
        }
        __syncthreads();
        if (s_kn != s_ko) {      // block repair: 1 element per thread
            int kn = s_kn, ko = s_ko;
            float xv = xs_[t];
            float nn = __fadd_rn(e[(size_t)kn * D_DIM + t], -xv);
            out[(size_t)row * D_DIM + t] = __fadd_rn(xv, nn);
            float oo = __fadd_rn(e[(size_t)ko * D_DIM + t], -xv);
            float ds = nn * nn - oo * oo;
            #pragma unroll
            for (int m = 16; m; m >>= 1) ds += __shfl_xor_sync(~0u, ds, m);
            if (lane == 0) wk[w] = ds;
            __syncthreads();
            if (t == 0) {
                float s = 0.f;
                #pragma unroll
                for (int q = 0; q < 8; q++) s += wk[q];
                atomicAdd(&g_sumsq, (double)s);
            }
        }
        __syncthreads();
    }
}

__global__ void vq_finalize_kernel(float* __restrict__ out_scalars, int n_vec)
{
    __shared__ float red[32];
    const int t = threadIdx.x;
    float p = (float)g_counts[t] / (float)n_vec;
    float s = p * logf(p + 1e-10f);
    #pragma unroll
    for (int m = 16; m; m >>= 1) s += __shfl_xor_sync(~0u, s, m);
    int lane = t & 31, w = t >> 5;
    if (lane == 0) red[w] = s;
    __syncthreads();
    if (t < 32) {
        float t2 = red[t];
        #pragma unroll
        for (int m = 16; m; m >>= 1) t2 += __shfl_xor_sync(~0u, t2, m);
        if (t == 0) {
            double mse = g_sumsq / ((double)n_vec * (double)D_DIM);
            out_scalars[0] = (float)(1.25 * mse);
            out_scalars[1] = expf(-t2);
        }
    }
}

extern "C" void kernel_launch(void* const* d_in, const int* in_sizes, int n_in,
                              void* d_out, int out_size)
{
    const float* x = (const float*)d_in[0];
    const float* e = (const float*)d_in[1];
    float* out = (float*)d_out;
    const int n_vec = in_sizes[0] / D_DIM;    // 65536

    static const int kScreenSmem = SM_FLOATS * (int)sizeof(float);   // 162816
    cudaFuncSetAttribute(vq_screen_kernel,
                         cudaFuncAttributeMaxDynamicSharedMemorySize, kScreenSmem);

    vq_zero_kernel<<<1, K_CB>>>();                                  // 1
    vq_cvt_e_enorm<<<K_CB / 4, 256>>>(e);                           // 2
    vq_screen_kernel<<<n_vec / 128, 512, kScreenSmem>>>(x, e, out); // 3
    vq_cheap_kernel<<<128, 256>>>(x, e, out);                       // 4 <- profiled
    vq_full_kernel<<<64, 256>>>(x, e, out);                         // 5
    vq_finalize_kernel<<<1, K_CB>>>(out + (size_t)n_vec * D_DIM, n_vec); // 6
}